// round 1
// baseline (speedup 1.0000x reference)
#include <cuda_runtime.h>

#define T 4
#define H 128
#define W 128
#define NCI 16
#define NCIN 64
#define PS 7
#define WSZ 27
#define NQ 1024
#define KSEL 100
#define PITCH 33
#define PD 784   // NCI*PS*PS

__device__ float v1g[T * NCI * H * W];
__device__ float v2g[T * NCI * H * W];
__device__ float zbuf[T * NQ * PD];

// ---------------------------------------------------------------------------
// Kernel 1: fused 3x3 conv (v1) + 1x1 conv (v2), 64ch -> 16ch
// grid (64 tiles of 16x16, T), 256 threads
// ---------------------------------------------------------------------------
__global__ void __launch_bounds__(256) conv_kernel(
    const float* __restrict__ vid, const float* __restrict__ gw,
    const float* __restrict__ gb, const float* __restrict__ thw,
    const float* __restrict__ thb)
{
    extern __shared__ float sm[];
    float* wsm  = sm;              // [64][9][16] co-contiguous = 9216 f
    float* thsm = sm + 9216;       // [64][16]                  = 1024 f
    float* tsm  = sm + 10240;      // [8][18][18]               = 2592 f

    int tid = threadIdx.x;
    int t = blockIdx.y;
    int tile = blockIdx.x;
    int ty0 = (tile >> 3) * 16, tx0 = (tile & 7) * 16;

    // weights: gw layout [co][cin][ky][kx] -> wsm[(cin*9+k)*16 + co]
    for (int n = tid; n < NCI * NCIN * 9; n += 256) {
        int co = n / 576, r = n - co * 576;
        int cin = r / 9, k = r - cin * 9;
        wsm[(cin * 9 + k) * 16 + co] = gw[n];
    }
    // theta: thw layout [co][cin] -> thsm[cin*16 + co]
    for (int n = tid; n < NCI * NCIN; n += 256) {
        int co = n >> 6, cin = n & 63;
        thsm[cin * 16 + co] = thw[co * 64 + cin];
    }

    float acc1[16], acc2[16];
#pragma unroll
    for (int i = 0; i < 16; i++) { acc1[i] = 0.f; acc2[i] = 0.f; }

    int py = tid >> 4, px = tid & 15;
    int gy = ty0 + py, gx = tx0 + px;

    for (int c0 = 0; c0 < NCIN; c0 += 8) {
        __syncthreads();
        for (int n = tid; n < 8 * 18 * 18; n += 256) {
            int cc = n / 324, r = n - cc * 324;
            int yy = r / 18, xx = r - yy * 18;
            int iy = ty0 + yy - 1, ix = tx0 + xx - 1;
            float v = 0.f;
            if (iy >= 0 && iy < H && ix >= 0 && ix < W)
                v = vid[((t * NCIN + c0 + cc) * H + iy) * W + ix];
            tsm[n] = v;
        }
        __syncthreads();
#pragma unroll
        for (int cc = 0; cc < 8; cc++) {
            const float* tp = &tsm[cc * 324 + py * 18 + px];
            float v[9];
            v[0] = tp[0];  v[1] = tp[1];  v[2] = tp[2];
            v[3] = tp[18]; v[4] = tp[19]; v[5] = tp[20];
            v[6] = tp[36]; v[7] = tp[37]; v[8] = tp[38];
            const float4* wp = reinterpret_cast<const float4*>(&wsm[(c0 + cc) * 144]);
#pragma unroll
            for (int k = 0; k < 9; k++) {
                float vv = v[k];
#pragma unroll
                for (int q4 = 0; q4 < 4; q4++) {
                    float4 w4 = wp[k * 4 + q4];
                    acc1[q4 * 4 + 0] += vv * w4.x;
                    acc1[q4 * 4 + 1] += vv * w4.y;
                    acc1[q4 * 4 + 2] += vv * w4.z;
                    acc1[q4 * 4 + 3] += vv * w4.w;
                }
            }
            float vc = v[4];
            const float4* tp4 = reinterpret_cast<const float4*>(&thsm[(c0 + cc) * 16]);
#pragma unroll
            for (int q4 = 0; q4 < 4; q4++) {
                float4 w4 = tp4[q4];
                acc2[q4 * 4 + 0] += vc * w4.x;
                acc2[q4 * 4 + 1] += vc * w4.y;
                acc2[q4 * 4 + 2] += vc * w4.z;
                acc2[q4 * 4 + 3] += vc * w4.w;
            }
        }
    }
#pragma unroll
    for (int co = 0; co < 16; co++) {
        int oidx = ((t * NCI + co) * H + gy) * W + gx;
        v1g[oidx] = acc1[co] + gb[co];
        v2g[oidx] = acc2[co] + thb[co];
    }
}

// ---------------------------------------------------------------------------
// Kernel 2: per-query fused scores + exact top-100 (jax tie order) + softmax
//           + zero-skip aggregation. grid (1024, T), 256 threads.
// ---------------------------------------------------------------------------
__global__ void __launch_bounds__(256) main_kernel()
{
    extern __shared__ float sm[];
    float* reg = sm;                                            // 16*33*33 = 17424 f
    float* qp  = sm + 17424;                                    // 16*7*8  = 896 f
    float* sc  = sm + 18320;                                    // 736 f
    unsigned long long* keys = (unsigned long long*)(sm + 19056); // 1024 * 8B
    float* wgt = sm + 21104;                                    // 100
    int*   cidx = (int*)(sm + 21204);                           // 100
    int*   cys  = (int*)(sm + 21304);                           // 100
    int*   cxs  = (int*)(sm + 21404);                           // 100
    float* red  = sm + 21504;                                   // 256
    // total 21760 floats = 87040 B

    int tid = threadIdx.x;
    int q = blockIdx.x, t = blockIdx.y;
    int qi = (q >> 5) << 2, qj = (q & 31) << 2;
    int r0 = max(qi - 13, 0), r1 = min(qi + 19, H - 1);
    int c0 = max(qj - 13, 0), c1 = min(qj + 19, W - 1);
    int RH = r1 - r0 + 1, RW = c1 - c0 + 1;
    int area = RH * RW;

    // ---- stage v1 region ----
    const float* v1t = v1g + t * NCI * H * W;
    for (int n = tid; n < NCI * area; n += 256) {
        int ci = n / area, m = n - ci * area;
        int y = m / RW, x = m - y * RW;
        reg[ci * 1089 + y * PITCH + x] = v1t[(ci * H + r0 + y) * W + c0 + x];
    }
    __syncthreads();

    // ---- query patch (clamped), padded rows of 8 for float4 ----
    for (int d = tid; d < PD; d += 256) {
        int ci = d / 49, r = d - ci * 49, pi = r / 7, pj = r - pi * 7;
        int yy = min(qi - r0 + pi, RH - 1);
        int xx = min(qj - c0 + pj, RW - 1);
        qp[(ci * 7 + pi) * 8 + pj] = reg[ci * 1089 + yy * PITCH + xx];
    }
    for (int n = tid; n < 112; n += 256) qp[n * 8 + 7] = 0.f;
    __syncthreads();

    // ---- 729 candidate scores ----
    for (int myc = tid; myc < WSZ * WSZ; myc += 256) {
        int oy = myc / WSZ, ox = myc - oy * WSZ;
        int cyr = min(max(qi + oy - 13, 0), H - 1) - r0;
        int cxr = min(max(qj + ox - 13, 0), W - 1) - c0;
        float acc = 0.f;
        bool xint = (cxr + 6 < RW);
#pragma unroll 1
        for (int ci = 0; ci < NCI; ci++) {
            const float* rb = reg + ci * 1089;
            const float4* qv = reinterpret_cast<const float4*>(qp + ci * 56);
#pragma unroll
            for (int pi = 0; pi < 7; pi++) {
                int ry = min(cyr + pi, RH - 1);
                const float* row = rb + ry * PITCH;
                float4 a = qv[pi * 2];
                float4 b = qv[pi * 2 + 1];
                if (xint) {
                    const float* p = row + cxr;
                    acc += a.x * p[0] + a.y * p[1] + a.z * p[2] + a.w * p[3]
                         + b.x * p[4] + b.y * p[5] + b.z * p[6];
                } else {
                    acc += a.x * row[cxr]
                         + a.y * row[min(cxr + 1, RW - 1)]
                         + a.z * row[min(cxr + 2, RW - 1)]
                         + a.w * row[min(cxr + 3, RW - 1)]
                         + b.x * row[min(cxr + 4, RW - 1)]
                         + b.y * row[min(cxr + 5, RW - 1)]
                         + b.z * row[min(cxr + 6, RW - 1)];
                }
            }
        }
        sc[myc] = acc;
    }
    __syncthreads();

    // ---- build sort keys: (value desc, cand idx asc) -> ascending u64 ----
    for (int i = tid; i < 1024; i += 256) {
        unsigned long long kk;
        if (i < WSZ * WSZ) {
            unsigned int b = __float_as_uint(sc[i]);
            unsigned int u = (b & 0x80000000u) ? ~b : (b | 0x80000000u);
            kk = (((unsigned long long)(~u)) << 32) | (unsigned int)i;
        } else {
            kk = 0xFFFFFFFFFFFFFFFFull;
        }
        keys[i] = kk;
    }
    __syncthreads();

    // ---- bitonic sort 1024 ----
    for (int k = 2; k <= 1024; k <<= 1) {
        for (int j = k >> 1; j > 0; j >>= 1) {
            for (int i = tid; i < 1024; i += 256) {
                int ixj = i ^ j;
                if (ixj > i) {
                    bool up = ((i & k) == 0);
                    unsigned long long a = keys[i], b = keys[ixj];
                    if ((a > b) == up) { keys[i] = b; keys[ixj] = a; }
                }
            }
            __syncthreads();
        }
    }

    // ---- softmax over top-100 ----
    float vmax = sc[(int)(keys[0] & 0xFFFFFFFFull)];
    float e = 0.f;
    if (tid < KSEL) {
        int c = (int)(keys[tid] & 0xFFFFFFFFull);
        cidx[tid] = c;
        int oy = c / WSZ, ox = c - oy * WSZ;
        cys[tid] = min(max(qi + oy - 13, 0), H - 1) - r0;
        cxs[tid] = min(max(qj + ox - 13, 0), W - 1) - c0;
        e = expf((sc[c] - vmax) * 10.f);
        wgt[tid] = e;
    }
    red[tid] = e;
    __syncthreads();
    for (int s = 128; s > 0; s >>= 1) {
        if (tid < s) red[tid] += red[tid + s];
        __syncthreads();
    }
    float inv = 1.f / red[0];
    __syncthreads();

    // ---- reload region with v2 ----
    const float* v2t = v2g + t * NCI * H * W;
    for (int n = tid; n < NCI * area; n += 256) {
        int ci = n / area, m = n - ci * area;
        int y = m / RW, x = m - y * RW;
        reg[ci * 1089 + y * PITCH + x] = v2t[(ci * H + r0 + y) * W + c0 + x];
    }
    __syncthreads();

    // ---- aggregation: z[d] = sum_k wgt_k * P2[ind_k][d]  (skip exact zeros) ----
    float* zp = zbuf + (t * NQ + q) * PD;
    for (int d = tid; d < PD; d += 256) {
        int ci = d / 49, r = d - ci * 49, pi = r / 7, pj = r - pi * 7;
        const float* rb = reg + ci * 1089;
        float acc = 0.f;
        for (int k = 0; k < KSEL; k++) {
            float w = wgt[k];
            if (w == 0.f) continue;
            int ry = min(cys[k] + pi, RH - 1);
            int rx = min(cxs[k] + pj, RW - 1);
            acc += w * rb[ry * PITCH + rx];
        }
        zp[d] = acc * inv;
    }
}

// ---------------------------------------------------------------------------
// Kernel 3: deterministic overlap-add gather + normalize by Zc
// ---------------------------------------------------------------------------
__global__ void __launch_bounds__(256) final_kernel(float* __restrict__ out)
{
    int idx = blockIdx.x * 256 + threadIdx.x;
    if (idx >= T * NCI * H * W) return;
    int x = idx & 127;
    int y = (idx >> 7) & 127;
    int ci = (idx >> 14) & 15;
    int t = idx >> 18;

    int ai[4], api[4], ni = 0;
    if (y == 127) {
        ai[0] = ai[1] = ai[2] = ai[3] = 31;
        api[0] = 3; api[1] = 4; api[2] = 5; api[3] = 6; ni = 4;
    } else {
        for (int p = (y & 3); p < 7; p += 4) {
            int a = (y - p) >> 2;
            if (y - p >= 0) { ai[ni] = a; api[ni] = p; ni++; }
        }
    }
    int aj[4], apj[4], nj = 0;
    if (x == 127) {
        aj[0] = aj[1] = aj[2] = aj[3] = 31;
        apj[0] = 3; apj[1] = 4; apj[2] = 5; apj[3] = 6; nj = 4;
    } else {
        for (int p = (x & 3); p < 7; p += 4) {
            int a = (x - p) >> 2;
            if (x - p >= 0) { aj[nj] = a; apj[nj] = p; nj++; }
        }
    }

    float acc = 0.f;
    for (int u = 0; u < ni; u++) {
        for (int v = 0; v < nj; v++) {
            int q = ai[u] * 32 + aj[v];
            int d = ci * 49 + api[u] * 7 + apj[v];
            acc += zbuf[((t << 10) + q) * PD + d];
        }
    }
    out[idx] = acc / (float)(ni * nj);
}

// ---------------------------------------------------------------------------
extern "C" void kernel_launch(void* const* d_in, const int* in_sizes, int n_in,
                              void* d_out, int out_size)
{
    const float* vid = (const float*)d_in[0];
    const float* gw  = (const float*)d_in[1];
    const float* gb  = (const float*)d_in[2];
    const float* thw = (const float*)d_in[3];
    const float* thb = (const float*)d_in[4];
    float* out = (float*)d_out;

    int conv_sm = (9216 + 1024 + 2592) * 4;   // 51328 B
    int main_sm = 21760 * 4;                   // 87040 B
    cudaFuncSetAttribute(conv_kernel, cudaFuncAttributeMaxDynamicSharedMemorySize, conv_sm);
    cudaFuncSetAttribute(main_kernel, cudaFuncAttributeMaxDynamicSharedMemorySize, main_sm);

    conv_kernel<<<dim3(64, T), 256, conv_sm>>>(vid, gw, gb, thw, thb);
    main_kernel<<<dim3(NQ, T), 256, main_sm>>>();
    int ntot = T * NCI * H * W;
    final_kernel<<<(ntot + 255) / 256, 256>>>(out);
}

// round 2
// speedup vs baseline: 1.1003x; 1.1003x over previous
#include <cuda_runtime.h>

#define T 4
#define H 128
#define W 128
#define NCI 16
#define NCIN 64
#define PS 7
#define WSZ 27
#define NQ 1024
#define KSEL 100
#define PITCH 33
#define PD 784   // NCI*PS*PS

__device__ float v1g[T * NCI * H * W];
__device__ float v2g[T * NCI * H * W];
__device__ float zbuf[T * NQ * PD];

// ---------------------------------------------------------------------------
// Kernel 1: fused 3x3 conv (v1) + 1x1 conv (v2), 64ch -> 16ch
// ---------------------------------------------------------------------------
__global__ void __launch_bounds__(256) conv_kernel(
    const float* __restrict__ vid, const float* __restrict__ gw,
    const float* __restrict__ gb, const float* __restrict__ thw,
    const float* __restrict__ thb)
{
    extern __shared__ float sm[];
    float* wsm  = sm;              // [64][9][16] = 9216 f
    float* thsm = sm + 9216;       // [64][16]    = 1024 f
    float* tsm  = sm + 10240;      // [8][18][18] = 2592 f

    int tid = threadIdx.x;
    int t = blockIdx.y;
    int tile = blockIdx.x;
    int ty0 = (tile >> 3) * 16, tx0 = (tile & 7) * 16;

    for (int n = tid; n < NCI * NCIN * 9; n += 256) {
        int co = n / 576, r = n - co * 576;
        int cin = r / 9, k = r - cin * 9;
        wsm[(cin * 9 + k) * 16 + co] = gw[n];
    }
    for (int n = tid; n < NCI * NCIN; n += 256) {
        int co = n >> 6, cin = n & 63;
        thsm[cin * 16 + co] = thw[co * 64 + cin];
    }

    float acc1[16], acc2[16];
#pragma unroll
    for (int i = 0; i < 16; i++) { acc1[i] = 0.f; acc2[i] = 0.f; }

    int py = tid >> 4, px = tid & 15;
    int gy = ty0 + py, gx = tx0 + px;

    for (int c0 = 0; c0 < NCIN; c0 += 8) {
        __syncthreads();
        for (int n = tid; n < 8 * 18 * 18; n += 256) {
            int cc = n / 324, r = n - cc * 324;
            int yy = r / 18, xx = r - yy * 18;
            int iy = ty0 + yy - 1, ix = tx0 + xx - 1;
            float v = 0.f;
            if (iy >= 0 && iy < H && ix >= 0 && ix < W)
                v = vid[((t * NCIN + c0 + cc) * H + iy) * W + ix];
            tsm[n] = v;
        }
        __syncthreads();
#pragma unroll
        for (int cc = 0; cc < 8; cc++) {
            const float* tp = &tsm[cc * 324 + py * 18 + px];
            float v[9];
            v[0] = tp[0];  v[1] = tp[1];  v[2] = tp[2];
            v[3] = tp[18]; v[4] = tp[19]; v[5] = tp[20];
            v[6] = tp[36]; v[7] = tp[37]; v[8] = tp[38];
            const float4* wp = reinterpret_cast<const float4*>(&wsm[(c0 + cc) * 144]);
#pragma unroll
            for (int k = 0; k < 9; k++) {
                float vv = v[k];
#pragma unroll
                for (int q4 = 0; q4 < 4; q4++) {
                    float4 w4 = wp[k * 4 + q4];
                    acc1[q4 * 4 + 0] += vv * w4.x;
                    acc1[q4 * 4 + 1] += vv * w4.y;
                    acc1[q4 * 4 + 2] += vv * w4.z;
                    acc1[q4 * 4 + 3] += vv * w4.w;
                }
            }
            float vc = v[4];
            const float4* tp4 = reinterpret_cast<const float4*>(&thsm[(c0 + cc) * 16]);
#pragma unroll
            for (int q4 = 0; q4 < 4; q4++) {
                float4 w4 = tp4[q4];
                acc2[q4 * 4 + 0] += vc * w4.x;
                acc2[q4 * 4 + 1] += vc * w4.y;
                acc2[q4 * 4 + 2] += vc * w4.z;
                acc2[q4 * 4 + 3] += vc * w4.w;
            }
        }
    }
#pragma unroll
    for (int co = 0; co < 16; co++) {
        int oidx = ((t * NCI + co) * H + gy) * W + gx;
        v1g[oidx] = acc1[co] + gb[co];
        v2g[oidx] = acc2[co] + thb[co];
    }
}

// ---------------------------------------------------------------------------
// Kernel 2 smem layout (floats):
//   reg  : 0      .. 17424   (16 x 33 x 33)   [aliased by keys u64[1024] during sort]
//   qp   : 17424  .. 18320   (16*7*8)
//   sc   : 18320  .. 19056   (736)
//   wgt  : 19056  .. 19156
//   cyx  : 19156  .. 19256   (int, packed cy<<16|cx)
//   red  : 19256  .. 19264
//   nzc  : 19264  (int count)
//   nzi  : 19268  .. 19368   (int)
// total 19376 floats = 77504 B  -> 3 CTAs/SM
// ---------------------------------------------------------------------------
#define SMF 19376

__device__ __forceinline__ void stage_region(
    const float* __restrict__ src, float* __restrict__ reg,
    int r0, int c0, int RH, int RW, int w5, int lane)
{
#pragma unroll 1
    for (int ci = 0; ci < NCI; ci++) {
        for (int y = w5; y < RH; y += 8) {
            const float* srow = src + (ci * H + r0 + y) * W + c0;
            float* drow = reg + ci * 1089 + y * PITCH;
            for (int x = lane; x < RW; x += 32) drow[x] = srow[x];
        }
    }
}

__global__ void __launch_bounds__(256) main_kernel()
{
    extern __shared__ float sm[];
    float* reg = sm;
    float* qp  = sm + 17424;
    float* sc  = sm + 18320;
    float* wgt = sm + 19056;
    int*   cyx = (int*)(sm + 19156);
    float* red = sm + 19256;
    int*   nzc = (int*)(sm + 19264);
    int*   nzi = (int*)(sm + 19268);
    unsigned long long* keys = (unsigned long long*)sm;   // alias over reg

    int tid = threadIdx.x;
    int w5 = tid >> 5, lane = tid & 31;
    int q = blockIdx.x, t = blockIdx.y;
    int qi = (q >> 5) << 2, qj = (q & 31) << 2;
    bool interior = (qi >= 16) && (qi <= 108) && (qj >= 16) && (qj <= 108);
    int r0 = max(qi - 13, 0), r1 = min(qi + 19, H - 1);
    int c0 = max(qj - 13, 0), c1 = min(qj + 19, W - 1);
    int RH = r1 - r0 + 1, RW = c1 - c0 + 1;

    // ---- stage v1 region ----
    stage_region(v1g + t * NCI * H * W, reg, r0, c0, RH, RW, w5, lane);
    __syncthreads();

    // ---- query patch, padded rows of 8 for float4 ----
    if (tid < 224) {
        for (int d = tid; d < PD; d += 224) {
            int ci = d / 49, r = d - ci * 49, pi = r / 7, pj = r - pi * 7;
            int yy = min(qi - r0 + pi, RH - 1);
            int xx = min(qj - c0 + pj, RW - 1);
            qp[(ci * 7 + pi) * 8 + pj] = reg[ci * 1089 + yy * PITCH + xx];
        }
    }
    for (int n = tid; n < 112; n += 256) qp[n * 8 + 7] = 0.f;
    __syncthreads();

    // ---- 729 candidate scores: each thread (tid<243) does 3 x-adjacent ----
    if (tid < 243) {
        int oy = tid / 9, og = tid - oy * 9;
        int ox = og * 3;
        if (interior) {
            float a0 = 0.f, a1 = 0.f, a2 = 0.f;
            const float4* qv4 = reinterpret_cast<const float4*>(qp);
#pragma unroll 1
            for (int ci = 0; ci < NCI; ci++) {
                const float* base = reg + ci * 1089 + oy * PITCH + ox;
                const float4* qv = qv4 + ci * 14;
#pragma unroll
                for (int pi = 0; pi < 7; pi++) {
                    const float* row = base + pi * PITCH;
                    float r0v = row[0], r1v = row[1], r2v = row[2], r3v = row[3];
                    float r4v = row[4], r5v = row[5], r6v = row[6], r7v = row[7];
                    float r8v = row[8];
                    float4 a = qv[pi * 2], b = qv[pi * 2 + 1];
                    a0 += a.x * r0v + a.y * r1v + a.z * r2v + a.w * r3v
                        + b.x * r4v + b.y * r5v + b.z * r6v;
                    a1 += a.x * r1v + a.y * r2v + a.z * r3v + a.w * r4v
                        + b.x * r5v + b.y * r6v + b.z * r7v;
                    a2 += a.x * r2v + a.y * r3v + a.z * r4v + a.w * r5v
                        + b.x * r6v + b.y * r7v + b.z * r8v;
                }
            }
            int o = oy * WSZ + ox;
            sc[o] = a0; sc[o + 1] = a1; sc[o + 2] = a2;
        } else {
            int cyc = min(max(qi + oy - 13, 0), H - 1) - r0;
            int ry[7];
#pragma unroll
            for (int p = 0; p < 7; p++) ry[p] = min(cyc + p, RH - 1) * PITCH;
#pragma unroll 1
            for (int s = 0; s < 3; s++) {
                int oxs = ox + s;
                int cxc = min(max(qj + oxs - 13, 0), W - 1) - c0;
                int cx[7];
#pragma unroll
                for (int p = 0; p < 7; p++) cx[p] = min(cxc + p, RW - 1);
                float acc = 0.f;
                const float4* qv4 = reinterpret_cast<const float4*>(qp);
#pragma unroll 1
                for (int ci = 0; ci < NCI; ci++) {
                    const float* rb = reg + ci * 1089;
                    const float4* qv = qv4 + ci * 14;
#pragma unroll
                    for (int p = 0; p < 7; p++) {
                        const float* row = rb + ry[p];
                        float4 a = qv[2 * p], b = qv[2 * p + 1];
                        acc += a.x * row[cx[0]] + a.y * row[cx[1]]
                             + a.z * row[cx[2]] + a.w * row[cx[3]]
                             + b.x * row[cx[4]] + b.y * row[cx[5]]
                             + b.z * row[cx[6]];
                    }
                }
                sc[oy * WSZ + oxs] = acc;
            }
        }
    }
    __syncthreads();

    // ---- build sort keys (value desc, idx asc -> ascending u64) into reg alias ----
    for (int i = tid; i < 1024; i += 256) {
        unsigned long long kk;
        if (i < WSZ * WSZ) {
            unsigned int b = __float_as_uint(sc[i]);
            unsigned int u = (b & 0x80000000u) ? ~b : (b | 0x80000000u);
            kk = (((unsigned long long)(~u)) << 32) | (unsigned int)i;
        } else {
            kk = 0xFFFFFFFFFFFFFFFFull;
        }
        keys[i] = kk;
    }
    __syncthreads();

    // ---- bitonic sort 1024: warp-local for j<128, block-wide for j>=128 ----
#pragma unroll 1
    for (int k = 2; k <= 1024; k <<= 1) {
#pragma unroll 1
        for (int j = k >> 1; j > 0; j >>= 1) {
            if (j >= 128) {
                __syncthreads();
                for (int i = tid; i < 1024; i += 256) {
                    int ixj = i ^ j;
                    if (ixj > i) {
                        bool up = ((i & k) == 0);
                        unsigned long long a = keys[i], b = keys[ixj];
                        if ((a > b) == up) { keys[i] = b; keys[ixj] = a; }
                    }
                }
                __syncthreads();
            } else {
#pragma unroll
                for (int n = 0; n < 4; n++) {
                    int i = (w5 << 7) + (n << 5) + lane;
                    int ixj = i ^ j;
                    if (ixj > i) {
                        bool up = ((i & k) == 0);
                        unsigned long long a = keys[i], b = keys[ixj];
                        if ((a > b) == up) { keys[i] = b; keys[ixj] = a; }
                    }
                }
                __syncwarp();
            }
        }
    }
    __syncthreads();

    // ---- softmax over top-100 ----
    float vmax = sc[(int)(keys[0] & 0xFFFFFFFFull)];
    float e = 0.f;
    if (tid < KSEL) {
        int c = (int)(keys[tid] & 0xFFFFFFFFull);
        int oy = c / WSZ, ox = c - oy * WSZ;
        int cy = min(max(qi + oy - 13, 0), H - 1) - r0;
        int cx = min(max(qj + ox - 13, 0), W - 1) - c0;
        cyx[tid] = (cy << 16) | cx;
        e = expf((sc[c] - vmax) * 10.f);
        wgt[tid] = e;
    }
#pragma unroll
    for (int s = 16; s > 0; s >>= 1) e += __shfl_xor_sync(0xffffffffu, e, s);
    if (lane == 0) red[w5] = e;
    __syncthreads();
    float inv = 1.f / (red[0] + red[1] + red[2] + red[3]);

    // ---- compact nonzero weights (warp 0, deterministic order) ----
    if (tid < 32) {
        int cnt = 0;
        for (int b = 0; b < 128; b += 32) {
            int kk = b + tid;
            bool nz = (kk < KSEL) && (wgt[kk] != 0.f);
            unsigned m = __ballot_sync(0xffffffffu, nz);
            int pos = cnt + __popc(m & ((1u << tid) - 1u));
            if (nz) nzi[pos] = kk;
            cnt += __popc(m);
        }
        if (tid == 0) *nzc = cnt;
    }
    __syncthreads();
    int nnz = *nzc;
    __syncthreads();

    // ---- reload region with v2 (overwrites keys; extraction done) ----
    stage_region(v2g + t * NCI * H * W, reg, r0, c0, RH, RW, w5, lane);
    __syncthreads();

    // ---- aggregation: z[d] = (sum_m wgt * P2) * inv over nonzero weights ----
    float* zp = zbuf + (t * NQ + q) * PD;
    for (int d = tid; d < PD; d += 256) {
        int ci = d / 49, r = d - ci * 49, pi = r / 7, pj = r - pi * 7;
        const float* rb = reg + ci * 1089;
        float acc = 0.f;
        for (int m = 0; m < nnz; m++) {
            int kk = nzi[m];
            float w = wgt[kk];
            int p = cyx[kk];
            int ryv = min((p >> 16) + pi, RH - 1);
            int rxv = min((p & 0xFFFF) + pj, RW - 1);
            acc += w * rb[ryv * PITCH + rxv];
        }
        zp[d] = acc * inv;
    }
}

// ---------------------------------------------------------------------------
// Kernel 3: deterministic overlap-add gather + normalize by Zc
// ---------------------------------------------------------------------------
__global__ void __launch_bounds__(256) final_kernel(float* __restrict__ out)
{
    int idx = blockIdx.x * 256 + threadIdx.x;
    if (idx >= T * NCI * H * W) return;
    int x = idx & 127;
    int y = (idx >> 7) & 127;
    int ci = (idx >> 14) & 15;
    int t = idx >> 18;

    int ai[4], api[4], ni = 0;
    if (y == 127) {
        ai[0] = ai[1] = ai[2] = ai[3] = 31;
        api[0] = 3; api[1] = 4; api[2] = 5; api[3] = 6; ni = 4;
    } else {
        for (int p = (y & 3); p < 7; p += 4) {
            int a = (y - p) >> 2;
            if (y - p >= 0) { ai[ni] = a; api[ni] = p; ni++; }
        }
    }
    int aj[4], apj[4], nj = 0;
    if (x == 127) {
        aj[0] = aj[1] = aj[2] = aj[3] = 31;
        apj[0] = 3; apj[1] = 4; apj[2] = 5; apj[3] = 6; nj = 4;
    } else {
        for (int p = (x & 3); p < 7; p += 4) {
            int a = (x - p) >> 2;
            if (x - p >= 0) { aj[nj] = a; apj[nj] = p; nj++; }
        }
    }

    float acc = 0.f;
    for (int u = 0; u < ni; u++) {
        for (int v = 0; v < nj; v++) {
            int qq = ai[u] * 32 + aj[v];
            int d = ci * 49 + api[u] * 7 + apj[v];
            acc += zbuf[((t << 10) + qq) * PD + d];
        }
    }
    out[idx] = acc / (float)(ni * nj);
}

// ---------------------------------------------------------------------------
extern "C" void kernel_launch(void* const* d_in, const int* in_sizes, int n_in,
                              void* d_out, int out_size)
{
    const float* vid = (const float*)d_in[0];
    const float* gw  = (const float*)d_in[1];
    const float* gb  = (const float*)d_in[2];
    const float* thw = (const float*)d_in[3];
    const float* thb = (const float*)d_in[4];
    float* out = (float*)d_out;

    int conv_sm = (9216 + 1024 + 2592) * 4;
    int main_sm = SMF * 4;
    cudaFuncSetAttribute(conv_kernel, cudaFuncAttributeMaxDynamicSharedMemorySize, conv_sm);
    cudaFuncSetAttribute(main_kernel, cudaFuncAttributeMaxDynamicSharedMemorySize, main_sm);

    conv_kernel<<<dim3(64, T), 256, conv_sm>>>(vid, gw, gb, thw, thb);
    main_kernel<<<dim3(NQ, T), 256, main_sm>>>();
    int ntot = T * NCI * H * W;
    final_kernel<<<(ntot + 255) / 256, 256>>>(out);
}

// round 3
// speedup vs baseline: 1.6172x; 1.4698x over previous
#include <cuda_runtime.h>

#define T 4
#define H 128
#define W 128
#define NCI 16
#define NCIN 64
#define PS 7
#define WSZ 27
#define NQ 1024
#define KSEL 100
#define PITCH 33
#define PD 784   // NCI*PS*PS

__device__ float v1g[T * NCI * H * W];
__device__ float v2g[T * NCI * H * W];
__device__ float zbuf[T * NQ * PD];

// ---------------------------------------------------------------------------
// Kernel 0: no-op (shifts ncu -s5 -c1 capture slot so main_kernel gets profiled)
// ---------------------------------------------------------------------------
__global__ void nudge_kernel() {}

// ---------------------------------------------------------------------------
// Kernel 1: fused 3x3 conv (v1) + 1x1 conv (v2), 64ch -> 16ch
// ---------------------------------------------------------------------------
__global__ void __launch_bounds__(256) conv_kernel(
    const float* __restrict__ vid, const float* __restrict__ gw,
    const float* __restrict__ gb, const float* __restrict__ thw,
    const float* __restrict__ thb)
{
    extern __shared__ float sm[];
    float* wsm  = sm;              // [64][9][16] = 9216 f
    float* thsm = sm + 9216;       // [64][16]    = 1024 f
    float* tsm  = sm + 10240;      // [8][18][18] = 2592 f

    int tid = threadIdx.x;
    int t = blockIdx.y;
    int tile = blockIdx.x;
    int ty0 = (tile >> 3) * 16, tx0 = (tile & 7) * 16;

    for (int n = tid; n < NCI * NCIN * 9; n += 256) {
        int co = n / 576, r = n - co * 576;
        int cin = r / 9, k = r - cin * 9;
        wsm[(cin * 9 + k) * 16 + co] = gw[n];
    }
    for (int n = tid; n < NCI * NCIN; n += 256) {
        int co = n >> 6, cin = n & 63;
        thsm[cin * 16 + co] = thw[co * 64 + cin];
    }

    float acc1[16], acc2[16];
#pragma unroll
    for (int i = 0; i < 16; i++) { acc1[i] = 0.f; acc2[i] = 0.f; }

    int py = tid >> 4, px = tid & 15;
    int gy = ty0 + py, gx = tx0 + px;

    for (int c0 = 0; c0 < NCIN; c0 += 8) {
        __syncthreads();
        for (int n = tid; n < 8 * 18 * 18; n += 256) {
            int cc = n / 324, r = n - cc * 324;
            int yy = r / 18, xx = r - yy * 18;
            int iy = ty0 + yy - 1, ix = tx0 + xx - 1;
            float v = 0.f;
            if (iy >= 0 && iy < H && ix >= 0 && ix < W)
                v = vid[((t * NCIN + c0 + cc) * H + iy) * W + ix];
            tsm[n] = v;
        }
        __syncthreads();
#pragma unroll
        for (int cc = 0; cc < 8; cc++) {
            const float* tp = &tsm[cc * 324 + py * 18 + px];
            float v[9];
            v[0] = tp[0];  v[1] = tp[1];  v[2] = tp[2];
            v[3] = tp[18]; v[4] = tp[19]; v[5] = tp[20];
            v[6] = tp[36]; v[7] = tp[37]; v[8] = tp[38];
            const float4* wp = reinterpret_cast<const float4*>(&wsm[(c0 + cc) * 144]);
#pragma unroll
            for (int k = 0; k < 9; k++) {
                float vv = v[k];
#pragma unroll
                for (int q4 = 0; q4 < 4; q4++) {
                    float4 w4 = wp[k * 4 + q4];
                    acc1[q4 * 4 + 0] += vv * w4.x;
                    acc1[q4 * 4 + 1] += vv * w4.y;
                    acc1[q4 * 4 + 2] += vv * w4.z;
                    acc1[q4 * 4 + 3] += vv * w4.w;
                }
            }
            float vc = v[4];
            const float4* tp4 = reinterpret_cast<const float4*>(&thsm[(c0 + cc) * 16]);
#pragma unroll
            for (int q4 = 0; q4 < 4; q4++) {
                float4 w4 = tp4[q4];
                acc2[q4 * 4 + 0] += vc * w4.x;
                acc2[q4 * 4 + 1] += vc * w4.y;
                acc2[q4 * 4 + 2] += vc * w4.z;
                acc2[q4 * 4 + 3] += vc * w4.w;
            }
        }
    }
#pragma unroll
    for (int co = 0; co < 16; co++) {
        int oidx = ((t * NCI + co) * H + gy) * W + gx;
        v1g[oidx] = acc1[co] + gb[co];
        v2g[oidx] = acc2[co] + thb[co];
    }
}

// ---------------------------------------------------------------------------
// Kernel 2 smem layout (floats):
//   reg : 0      .. 17424   (16 x 33 x 33)  [keys u64[1024] alias reg[0..2048)]
//   qp  : 17424  .. 18320   (16*7*8)        [wgt/cyx/red/nzc/nzi alias qp after score]
//   sc  : 18320  .. 19049   (729)
// total 19056 floats = 76224 B  -> 3 CTAs/SM
// ---------------------------------------------------------------------------
#define SMF 19056

__device__ __forceinline__ void stage_v1(
    const float* __restrict__ src, float* __restrict__ reg,
    int r0, int c0, int RH, int RW, int w5, int lane)
{
    bool full = (RW == 33);
    const float* sb = src + r0 * W + c0;
#pragma unroll 2
    for (int ci = 0; ci < NCI; ci++) {
        const float* sbase = sb + ci * (H * W);
        float* dbase = reg + ci * 1089;
#pragma unroll 2
        for (int y = w5; y < RH; y += 8) {
            const float* srow = sbase + y * W;
            float* drow = dbase + y * PITCH;
            if (lane < RW) drow[lane] = srow[lane];
            if (full && lane == 0) drow[32] = srow[32];
        }
    }
}

__global__ void __launch_bounds__(256, 3) main_kernel()
{
    extern __shared__ float sm[];
    float* reg = sm;
    float* qp  = sm + 17424;
    float* sc  = sm + 18320;
    // aliases (live only after score phase):
    unsigned long long* keys = (unsigned long long*)sm;   // over reg[0..2048)
    float* wgt = qp;                                      // 100
    int*   cyx = (int*)(qp + 100);                        // 100 (abs cy<<16|cx)
    float* red = qp + 200;                                // 8
    int*   nzc = (int*)(qp + 208);                        // 1
    int*   nzi = (int*)(qp + 212);                        // 100

    int tid = threadIdx.x;
    int w5 = tid >> 5, lane = tid & 31;
    int q = blockIdx.x, t = blockIdx.y;
    int qi = (q >> 5) << 2, qj = (q & 31) << 2;
    bool interior = (qi >= 16) && (qi <= 108) && (qj >= 16) && (qj <= 108);
    int r0 = max(qi - 13, 0), r1 = min(qi + 19, H - 1);
    int c0 = max(qj - 13, 0), c1 = min(qj + 19, W - 1);
    int RH = r1 - r0 + 1, RW = c1 - c0 + 1;

    // ---- stage v1 region (warp-per-row, high MLP) ----
    stage_v1(v1g + t * NCI * H * W, reg, r0, c0, RH, RW, w5, lane);
    __syncthreads();

    // ---- query patch, padded rows of 8 for float4 ----
    if (tid < 224) {
        for (int d = tid; d < PD; d += 224) {
            int ci = d / 49, r = d - ci * 49, pi = r / 7, pj = r - pi * 7;
            int yy = min(qi - r0 + pi, RH - 1);
            int xx = min(qj - c0 + pj, RW - 1);
            qp[(ci * 7 + pi) * 8 + pj] = reg[ci * 1089 + yy * PITCH + xx];
        }
    }
    for (int n = tid; n < 112; n += 256) qp[n * 8 + 7] = 0.f;
    __syncthreads();

    // ---- 729 candidate scores: each thread (tid<243) does 3 x-adjacent ----
    if (tid < 243) {
        int oy = tid / 9, og = tid - oy * 9;
        int ox = og * 3;
        if (interior) {
            float a0 = 0.f, a1 = 0.f, a2 = 0.f;
            const float4* qv4 = reinterpret_cast<const float4*>(qp);
#pragma unroll 1
            for (int ci = 0; ci < NCI; ci++) {
                const float* base = reg + ci * 1089 + oy * PITCH + ox;
                const float4* qv = qv4 + ci * 14;
#pragma unroll
                for (int pi = 0; pi < 7; pi++) {
                    const float* row = base + pi * PITCH;
                    float r0v = row[0], r1v = row[1], r2v = row[2], r3v = row[3];
                    float r4v = row[4], r5v = row[5], r6v = row[6], r7v = row[7];
                    float r8v = row[8];
                    float4 a = qv[pi * 2], b = qv[pi * 2 + 1];
                    a0 += a.x * r0v + a.y * r1v + a.z * r2v + a.w * r3v
                        + b.x * r4v + b.y * r5v + b.z * r6v;
                    a1 += a.x * r1v + a.y * r2v + a.z * r3v + a.w * r4v
                        + b.x * r5v + b.y * r6v + b.z * r7v;
                    a2 += a.x * r2v + a.y * r3v + a.z * r4v + a.w * r5v
                        + b.x * r6v + b.y * r7v + b.z * r8v;
                }
            }
            int o = oy * WSZ + ox;
            sc[o] = a0; sc[o + 1] = a1; sc[o + 2] = a2;
        } else {
            int cyc = min(max(qi + oy - 13, 0), H - 1) - r0;
            int ry[7];
#pragma unroll
            for (int p = 0; p < 7; p++) ry[p] = min(cyc + p, RH - 1) * PITCH;
#pragma unroll 1
            for (int s = 0; s < 3; s++) {
                int oxs = ox + s;
                int cxc = min(max(qj + oxs - 13, 0), W - 1) - c0;
                int cx[7];
#pragma unroll
                for (int p = 0; p < 7; p++) cx[p] = min(cxc + p, RW - 1);
                float acc = 0.f;
                const float4* qv4 = reinterpret_cast<const float4*>(qp);
#pragma unroll 1
                for (int ci = 0; ci < NCI; ci++) {
                    const float* rb = reg + ci * 1089;
                    const float4* qv = qv4 + ci * 14;
#pragma unroll
                    for (int p = 0; p < 7; p++) {
                        const float* row = rb + ry[p];
                        float4 a = qv[2 * p], b = qv[2 * p + 1];
                        acc += a.x * row[cx[0]] + a.y * row[cx[1]]
                             + a.z * row[cx[2]] + a.w * row[cx[3]]
                             + b.x * row[cx[4]] + b.y * row[cx[5]]
                             + b.z * row[cx[6]];
                    }
                }
                sc[oy * WSZ + oxs] = acc;
            }
        }
    }
    __syncthreads();

    // ---- build sort keys (value desc, idx asc -> ascending u64) over reg alias ----
    for (int i = tid; i < 1024; i += 256) {
        unsigned long long kk;
        if (i < WSZ * WSZ) {
            unsigned int b = __float_as_uint(sc[i]);
            unsigned int u = (b & 0x80000000u) ? ~b : (b | 0x80000000u);
            kk = (((unsigned long long)(~u)) << 32) | (unsigned int)i;
        } else {
            kk = 0xFFFFFFFFFFFFFFFFull;
        }
        keys[i] = kk;
    }
    __syncthreads();

    // ---- bitonic sort 1024: warp-local for j<128, block-wide for j>=128 ----
#pragma unroll 1
    for (int k = 2; k <= 1024; k <<= 1) {
#pragma unroll 1
        for (int j = k >> 1; j > 0; j >>= 1) {
            if (j >= 128) {
                __syncthreads();
                for (int i = tid; i < 1024; i += 256) {
                    int ixj = i ^ j;
                    if (ixj > i) {
                        bool up = ((i & k) == 0);
                        unsigned long long a = keys[i], b = keys[ixj];
                        if ((a > b) == up) { keys[i] = b; keys[ixj] = a; }
                    }
                }
                __syncthreads();
            } else {
#pragma unroll
                for (int n = 0; n < 4; n++) {
                    int i = (w5 << 7) + (n << 5) + lane;
                    int ixj = i ^ j;
                    if (ixj > i) {
                        bool up = ((i & k) == 0);
                        unsigned long long a = keys[i], b = keys[ixj];
                        if ((a > b) == up) { keys[i] = b; keys[ixj] = a; }
                    }
                }
                __syncwarp();
            }
        }
    }
    __syncthreads();

    // ---- softmax over top-100 (wgt/cyx alias qp: qp is dead now) ----
    float vmax = sc[(int)(keys[0] & 0xFFFFFFFFull)];
    float e = 0.f;
    int csel = 0;
    if (tid < KSEL) csel = (int)(keys[tid] & 0xFFFFFFFFull);
    __syncthreads();   // keys fully read before any (none) reuse; qp aliases safe
    if (tid < KSEL) {
        int oy = csel / WSZ, ox = csel - oy * WSZ;
        int cy = min(max(qi + oy - 13, 0), H - 1);
        int cx = min(max(qj + ox - 13, 0), W - 1);
        cyx[tid] = (cy << 16) | cx;
        e = expf((sc[csel] - vmax) * 10.f);
        wgt[tid] = e;
    }
#pragma unroll
    for (int s = 16; s > 0; s >>= 1) e += __shfl_xor_sync(0xffffffffu, e, s);
    if (lane == 0) red[w5] = e;
    __syncthreads();
    float inv = 1.f / (red[0] + red[1] + red[2] + red[3]);

    // ---- compact nonzero weights (warp 0, deterministic order) ----
    if (tid < 32) {
        int cnt = 0;
        for (int b = 0; b < 128; b += 32) {
            int kk = b + tid;
            bool nz = (kk < KSEL) && (wgt[kk] != 0.f);
            unsigned m = __ballot_sync(0xffffffffu, nz);
            int pos = cnt + __popc(m & ((1u << tid) - 1u));
            if (nz) nzi[pos] = kk;
            cnt += __popc(m);
        }
        if (tid == 0) *nzc = cnt;
    }
    __syncthreads();
    int nnz = *nzc;

    // ---- aggregation: read needed v2 patches DIRECTLY from global (L2) ----
    const float* v2t = v2g + t * NCI * H * W;
    float* zp = zbuf + (t * NQ + q) * PD;
    for (int d = tid; d < PD; d += 256) {
        int ci = d / 49, r = d - ci * 49, pi = r / 7, pj = r - pi * 7;
        const float* cb = v2t + ci * (H * W);
        float acc = 0.f;
        for (int m = 0; m < nnz; m++) {
            int kk = nzi[m];
            float w = wgt[kk];
            int p = cyx[kk];
            int ryv = min((p >> 16) + pi, H - 1);
            int rxv = min((p & 0xFFFF) + pj, W - 1);
            acc += w * cb[ryv * W + rxv];
        }
        zp[d] = acc * inv;
    }
}

// ---------------------------------------------------------------------------
// Kernel 3: deterministic overlap-add gather + normalize by Zc
// ---------------------------------------------------------------------------
__global__ void __launch_bounds__(256) final_kernel(float* __restrict__ out)
{
    int idx = blockIdx.x * 256 + threadIdx.x;
    if (idx >= T * NCI * H * W) return;
    int x = idx & 127;
    int y = (idx >> 7) & 127;
    int ci = (idx >> 14) & 15;
    int t = idx >> 18;

    int ai[4], api[4], ni = 0;
    if (y == 127) {
        ai[0] = ai[1] = ai[2] = ai[3] = 31;
        api[0] = 3; api[1] = 4; api[2] = 5; api[3] = 6; ni = 4;
    } else {
        for (int p = (y & 3); p < 7; p += 4) {
            int a = (y - p) >> 2;
            if (y - p >= 0) { ai[ni] = a; api[ni] = p; ni++; }
        }
    }
    int aj[4], apj[4], nj = 0;
    if (x == 127) {
        aj[0] = aj[1] = aj[2] = aj[3] = 31;
        apj[0] = 3; apj[1] = 4; apj[2] = 5; apj[3] = 6; nj = 4;
    } else {
        for (int p = (x & 3); p < 7; p += 4) {
            int a = (x - p) >> 2;
            if (x - p >= 0) { aj[nj] = a; apj[nj] = p; nj++; }
        }
    }

    float acc = 0.f;
    for (int u = 0; u < ni; u++) {
        for (int v = 0; v < nj; v++) {
            int qq = ai[u] * 32 + aj[v];
            int d = ci * 49 + api[u] * 7 + apj[v];
            acc += zbuf[((t << 10) + qq) * PD + d];
        }
    }
    out[idx] = acc / (float)(ni * nj);
}

// ---------------------------------------------------------------------------
extern "C" void kernel_launch(void* const* d_in, const int* in_sizes, int n_in,
                              void* d_out, int out_size)
{
    const float* vid = (const float*)d_in[0];
    const float* gw  = (const float*)d_in[1];
    const float* gb  = (const float*)d_in[2];
    const float* thw = (const float*)d_in[3];
    const float* thb = (const float*)d_in[4];
    float* out = (float*)d_out;

    int conv_sm = (9216 + 1024 + 2592) * 4;
    int main_sm = SMF * 4;
    cudaFuncSetAttribute(conv_kernel, cudaFuncAttributeMaxDynamicSharedMemorySize, conv_sm);
    cudaFuncSetAttribute(main_kernel, cudaFuncAttributeMaxDynamicSharedMemorySize, main_sm);

    nudge_kernel<<<1, 32>>>();
    conv_kernel<<<dim3(64, T), 256, conv_sm>>>(vid, gw, gb, thw, thb);
    main_kernel<<<dim3(NQ, T), 256, main_sm>>>();
    int ntot = T * NCI * H * W;
    final_kernel<<<(ntot + 255) / 256, 256>>>(out);
}

// round 4
// speedup vs baseline: 1.6966x; 1.0491x over previous
#include <cuda_runtime.h>

#define T 4
#define H 128
#define W 128
#define NCI 16
#define NCIN 64
#define PS 7
#define WSZ 27
#define NQ 1024
#define KSEL 100
#define PITCH 33
#define PD 784   // NCI*PS*PS

__device__ float v1g[T * NCI * H * W];
__device__ float v2g[T * NCI * H * W];
__device__ float zbuf[T * NQ * PD];

// ---------------------------------------------------------------------------
// Kernel 0: no-op (capture-slot alignment: index 15 -> main_kernel)
// ---------------------------------------------------------------------------
__global__ void nudge_kernel() {}

// ---------------------------------------------------------------------------
// Kernel 1: fused 3x3 conv (v1) + 1x1 conv (v2), 64ch -> 16ch
// ---------------------------------------------------------------------------
__global__ void __launch_bounds__(256) conv_kernel(
    const float* __restrict__ vid, const float* __restrict__ gw,
    const float* __restrict__ gb, const float* __restrict__ thw,
    const float* __restrict__ thb)
{
    extern __shared__ float sm[];
    float* wsm  = sm;              // [64][9][16] = 9216 f
    float* thsm = sm + 9216;       // [64][16]    = 1024 f
    float* tsm  = sm + 10240;      // [8][18][18] = 2592 f

    int tid = threadIdx.x;
    int t = blockIdx.y;
    int tile = blockIdx.x;
    int ty0 = (tile >> 3) * 16, tx0 = (tile & 7) * 16;

    for (int n = tid; n < NCI * NCIN * 9; n += 256) {
        int co = n / 576, r = n - co * 576;
        int cin = r / 9, k = r - cin * 9;
        wsm[(cin * 9 + k) * 16 + co] = gw[n];
    }
    for (int n = tid; n < NCI * NCIN; n += 256) {
        int co = n >> 6, cin = n & 63;
        thsm[cin * 16 + co] = thw[co * 64 + cin];
    }

    float acc1[16], acc2[16];
#pragma unroll
    for (int i = 0; i < 16; i++) { acc1[i] = 0.f; acc2[i] = 0.f; }

    int py = tid >> 4, px = tid & 15;
    int gy = ty0 + py, gx = tx0 + px;

    for (int c0 = 0; c0 < NCIN; c0 += 8) {
        __syncthreads();
        for (int n = tid; n < 8 * 18 * 18; n += 256) {
            int cc = n / 324, r = n - cc * 324;
            int yy = r / 18, xx = r - yy * 18;
            int iy = ty0 + yy - 1, ix = tx0 + xx - 1;
            float v = 0.f;
            if (iy >= 0 && iy < H && ix >= 0 && ix < W)
                v = vid[((t * NCIN + c0 + cc) * H + iy) * W + ix];
            tsm[n] = v;
        }
        __syncthreads();
#pragma unroll
        for (int cc = 0; cc < 8; cc++) {
            const float* tp = &tsm[cc * 324 + py * 18 + px];
            float v[9];
            v[0] = tp[0];  v[1] = tp[1];  v[2] = tp[2];
            v[3] = tp[18]; v[4] = tp[19]; v[5] = tp[20];
            v[6] = tp[36]; v[7] = tp[37]; v[8] = tp[38];
            const float4* wp = reinterpret_cast<const float4*>(&wsm[(c0 + cc) * 144]);
#pragma unroll
            for (int k = 0; k < 9; k++) {
                float vv = v[k];
#pragma unroll
                for (int q4 = 0; q4 < 4; q4++) {
                    float4 w4 = wp[k * 4 + q4];
                    acc1[q4 * 4 + 0] += vv * w4.x;
                    acc1[q4 * 4 + 1] += vv * w4.y;
                    acc1[q4 * 4 + 2] += vv * w4.z;
                    acc1[q4 * 4 + 3] += vv * w4.w;
                }
            }
            float vc = v[4];
            const float4* tp4 = reinterpret_cast<const float4*>(&thsm[(c0 + cc) * 16]);
#pragma unroll
            for (int q4 = 0; q4 < 4; q4++) {
                float4 w4 = tp4[q4];
                acc2[q4 * 4 + 0] += vc * w4.x;
                acc2[q4 * 4 + 1] += vc * w4.y;
                acc2[q4 * 4 + 2] += vc * w4.z;
                acc2[q4 * 4 + 3] += vc * w4.w;
            }
        }
    }
#pragma unroll
    for (int co = 0; co < 16; co++) {
        int oidx = ((t * NCI + co) * H + gy) * W + gx;
        v1g[oidx] = acc1[co] + gb[co];
        v2g[oidx] = acc2[co] + thb[co];
    }
}

// ---------------------------------------------------------------------------
// Kernel 2 smem (floats):
//   reg : 0    .. 8712    (8ch x 33 x 33)  [keys u64[1024] alias reg after score]
//   qp  : 8712 .. 9168    (8ch*7*8)        [wgt/cyx/red/nzc/nzi alias qp after score]
//   sc  : 9168 .. 9897    (729)
// total 9897 f = 39588 B -> 4 CTAs/SM (reg-limited), latency well hidden
// ---------------------------------------------------------------------------
#define SMF 9897

__device__ __forceinline__ void stage8(
    const float* __restrict__ src, float* __restrict__ reg,
    int r0, int c0, int RH, int RW, int w5, int lane)
{
    bool full = (RW == 33);
    const float* sb = src + r0 * W + c0;
#pragma unroll
    for (int ci = 0; ci < 8; ci++) {
        const float* sbase = sb + ci * (H * W);
        float* dbase = reg + ci * 1089;
#pragma unroll 2
        for (int y = w5; y < RH; y += 8) {
            const float* srow = sbase + y * W;
            float* drow = dbase + y * PITCH;
            if (lane < RW) drow[lane] = srow[lane];
            if (full && lane == 0) drow[32] = srow[32];
        }
    }
}

__global__ void __launch_bounds__(256, 4) main_kernel()
{
    extern __shared__ float sm[];
    float* reg = sm;
    float* qp  = sm + 8712;
    float* sc  = sm + 9168;
    // aliases:
    unsigned long long* keys = (unsigned long long*)sm;   // over reg[0..2048)
    float* wgt = qp;                                      // 100
    int*   cyx = (int*)(qp + 100);                        // 100 (abs cy<<16|cx)
    float* red = qp + 200;                                // 8
    int*   nzc = (int*)(qp + 208);                        // 1
    int*   nzi = (int*)(qp + 212);                        // 100

    int tid = threadIdx.x;
    int w5 = tid >> 5, lane = tid & 31;
    int q = blockIdx.x, t = blockIdx.y;
    int qi = (q >> 5) << 2, qj = (q & 31) << 2;
    bool interior = (qi >= 16) && (qi <= 108) && (qj >= 16) && (qj <= 108);
    int r0 = max(qi - 13, 0), r1 = min(qi + 19, H - 1);
    int c0 = max(qj - 13, 0), c1 = min(qj + 19, W - 1);
    int RH = r1 - r0 + 1, RW = c1 - c0 + 1;

    int oy = 0, ox = 0;
    if (tid < 243) { oy = tid / 9; ox = (tid - oy * 9) * 3; }

    float accv0 = 0.f, accv1 = 0.f, accv2 = 0.f;

#pragma unroll 1
    for (int pass = 0; pass < 2; pass++) {
        // ---- stage 8 channels of v1 ----
        stage8(v1g + (t * NCI + pass * 8) * H * W, reg, r0, c0, RH, RW, w5, lane);
        __syncthreads();

        // ---- query patch for these 8 channels (rows padded to 8) ----
        if (tid < 196) {
            for (int d = tid; d < 392; d += 196) {
                int ci = d / 49, r = d - ci * 49, pi = r / 7, pj = r - pi * 7;
                int yy = min(qi - r0 + pi, RH - 1);
                int xx = min(qj - c0 + pj, RW - 1);
                qp[(ci * 7 + pi) * 8 + pj] = reg[ci * 1089 + yy * PITCH + xx];
            }
        } else if (tid < 252) {
            qp[(tid - 196) * 8 + 7] = 0.f;
        }
        __syncthreads();

        // ---- partial scores over 8 channels ----
        if (tid < 243) {
            const float4* qv4 = reinterpret_cast<const float4*>(qp);
            if (interior) {
#pragma unroll 1
                for (int ci = 0; ci < 8; ci++) {
                    const float* base = reg + ci * 1089 + oy * PITCH + ox;
                    const float4* qv = qv4 + ci * 14;
#pragma unroll
                    for (int pi = 0; pi < 7; pi++) {
                        const float* row = base + pi * PITCH;
                        float r0v = row[0], r1v = row[1], r2v = row[2], r3v = row[3];
                        float r4v = row[4], r5v = row[5], r6v = row[6], r7v = row[7];
                        float r8v = row[8];
                        float4 a = qv[pi * 2], b = qv[pi * 2 + 1];
                        accv0 += a.x * r0v + a.y * r1v + a.z * r2v + a.w * r3v
                               + b.x * r4v + b.y * r5v + b.z * r6v;
                        accv1 += a.x * r1v + a.y * r2v + a.z * r3v + a.w * r4v
                               + b.x * r5v + b.y * r6v + b.z * r7v;
                        accv2 += a.x * r2v + a.y * r3v + a.z * r4v + a.w * r5v
                               + b.x * r6v + b.y * r7v + b.z * r8v;
                    }
                }
            } else {
                int cyc = min(max(qi + oy - 13, 0), H - 1) - r0;
                int ry[7];
#pragma unroll
                for (int p = 0; p < 7; p++) ry[p] = min(cyc + p, RH - 1) * PITCH;
#pragma unroll
                for (int s = 0; s < 3; s++) {
                    int oxs = ox + s;
                    int cxc = min(max(qj + oxs - 13, 0), W - 1) - c0;
                    int cx[7];
#pragma unroll
                    for (int p = 0; p < 7; p++) cx[p] = min(cxc + p, RW - 1);
                    float acc = 0.f;
#pragma unroll 1
                    for (int ci = 0; ci < 8; ci++) {
                        const float* rb = reg + ci * 1089;
                        const float4* qv = qv4 + ci * 14;
#pragma unroll
                        for (int p = 0; p < 7; p++) {
                            const float* row = rb + ry[p];
                            float4 a = qv[2 * p], b = qv[2 * p + 1];
                            acc += a.x * row[cx[0]] + a.y * row[cx[1]]
                                 + a.z * row[cx[2]] + a.w * row[cx[3]]
                                 + b.x * row[cx[4]] + b.y * row[cx[5]]
                                 + b.z * row[cx[6]];
                        }
                    }
                    if (s == 0) accv0 += acc;
                    else if (s == 1) accv1 += acc;
                    else accv2 += acc;
                }
            }
        }
        __syncthreads();   // before restage overwrites reg
    }

    if (tid < 243) {
        int o = oy * WSZ + ox;
        sc[o] = accv0; sc[o + 1] = accv1; sc[o + 2] = accv2;
    }
    __syncthreads();

    // ---- build sort keys (value desc, idx asc -> ascending u64) over reg alias ----
    for (int i = tid; i < 1024; i += 256) {
        unsigned long long kk;
        if (i < WSZ * WSZ) {
            unsigned int b = __float_as_uint(sc[i]);
            unsigned int u = (b & 0x80000000u) ? ~b : (b | 0x80000000u);
            kk = (((unsigned long long)(~u)) << 32) | (unsigned int)i;
        } else {
            kk = 0xFFFFFFFFFFFFFFFFull;
        }
        keys[i] = kk;
    }
    __syncthreads();

    // ---- bitonic sort 1024: warp-local for j<128, block-wide for j>=128 ----
#pragma unroll 1
    for (int k = 2; k <= 1024; k <<= 1) {
#pragma unroll 1
        for (int j = k >> 1; j > 0; j >>= 1) {
            if (j >= 128) {
                __syncthreads();
                for (int i = tid; i < 1024; i += 256) {
                    int ixj = i ^ j;
                    if (ixj > i) {
                        bool up = ((i & k) == 0);
                        unsigned long long a = keys[i], b = keys[ixj];
                        if ((a > b) == up) { keys[i] = b; keys[ixj] = a; }
                    }
                }
                __syncthreads();
            } else {
#pragma unroll
                for (int n = 0; n < 4; n++) {
                    int i = (w5 << 7) + (n << 5) + lane;
                    int ixj = i ^ j;
                    if (ixj > i) {
                        bool up = ((i & k) == 0);
                        unsigned long long a = keys[i], b = keys[ixj];
                        if ((a > b) == up) { keys[i] = b; keys[ixj] = a; }
                    }
                }
                __syncwarp();
            }
        }
    }
    __syncthreads();

    // ---- softmax over top-100 (wgt/... alias qp; qp dead) ----
    float vmax = sc[(int)(keys[0] & 0xFFFFFFFFull)];
    float e = 0.f;
    if (tid < KSEL) {
        int csel = (int)(keys[tid] & 0xFFFFFFFFull);
        int soy = csel / WSZ, sox = csel - soy * WSZ;
        int cy = min(max(qi + soy - 13, 0), H - 1);
        int cx = min(max(qj + sox - 13, 0), W - 1);
        cyx[tid] = (cy << 16) | cx;
        e = expf((sc[csel] - vmax) * 10.f);
        wgt[tid] = e;
    }
#pragma unroll
    for (int s = 16; s > 0; s >>= 1) e += __shfl_xor_sync(0xffffffffu, e, s);
    if (lane == 0) red[w5] = e;
    __syncthreads();
    float inv = 1.f / (red[0] + red[1] + red[2] + red[3]);

    // ---- compact nonzero weights (warp 0, deterministic order) ----
    if (tid < 32) {
        int cnt = 0;
        for (int b = 0; b < 128; b += 32) {
            int kk = b + tid;
            bool nz = (kk < KSEL) && (wgt[kk] != 0.f);
            unsigned m = __ballot_sync(0xffffffffu, nz);
            int pos = cnt + __popc(m & ((1u << tid) - 1u));
            if (nz) nzi[pos] = kk;
            cnt += __popc(m);
        }
        if (tid == 0) *nzc = cnt;
    }
    __syncthreads();
    int nnz = *nzc;

    // ---- aggregation: 4 d's per thread, MLP-4 L2 loads from v2 ----
    const float* v2t = v2g + t * NCI * H * W;
    float* zp = zbuf + (t * NQ + q) * PD;
    if (tid < 196) {
        int d0 = tid * 4;
        int cb[4], piu[4], pju[4];
#pragma unroll
        for (int u = 0; u < 4; u++) {
            int d = d0 + u;
            int ci = d / 49, r = d - ci * 49;
            piu[u] = r / 7; pju[u] = r - piu[u] * 7;
            cb[u] = ci * (H * W);
        }
        float acc[4] = {0.f, 0.f, 0.f, 0.f};
#pragma unroll 1
        for (int m = 0; m < nnz; m++) {
            int kk = nzi[m];
            float wv = wgt[kk];
            int p = cyx[kk];
            int cy = p >> 16, cx = p & 0xFFFF;
#pragma unroll
            for (int u = 0; u < 4; u++) {
                int ryv = min(cy + piu[u], H - 1);
                int rxv = min(cx + pju[u], W - 1);
                acc[u] += wv * v2t[cb[u] + ryv * W + rxv];
            }
        }
#pragma unroll
        for (int u = 0; u < 4; u++) zp[d0 + u] = acc[u] * inv;
    }
}

// ---------------------------------------------------------------------------
// Kernel 3: deterministic overlap-add gather + normalize by Zc
// ---------------------------------------------------------------------------
__global__ void __launch_bounds__(256) final_kernel(float* __restrict__ out)
{
    int idx = blockIdx.x * 256 + threadIdx.x;
    if (idx >= T * NCI * H * W) return;
    int x = idx & 127;
    int y = (idx >> 7) & 127;
    int ci = (idx >> 14) & 15;
    int t = idx >> 18;

    int ai[4], api[4], ni = 0;
    if (y == 127) {
        ai[0] = ai[1] = ai[2] = ai[3] = 31;
        api[0] = 3; api[1] = 4; api[2] = 5; api[3] = 6; ni = 4;
    } else {
        for (int p = (y & 3); p < 7; p += 4) {
            int a = (y - p) >> 2;
            if (y - p >= 0) { ai[ni] = a; api[ni] = p; ni++; }
        }
    }
    int aj[4], apj[4], nj = 0;
    if (x == 127) {
        aj[0] = aj[1] = aj[2] = aj[3] = 31;
        apj[0] = 3; apj[1] = 4; apj[2] = 5; apj[3] = 6; nj = 4;
    } else {
        for (int p = (x & 3); p < 7; p += 4) {
            int a = (x - p) >> 2;
            if (x - p >= 0) { aj[nj] = a; apj[nj] = p; nj++; }
        }
    }

    float acc = 0.f;
    for (int u = 0; u < ni; u++) {
        for (int v = 0; v < nj; v++) {
            int qq = ai[u] * 32 + aj[v];
            int d = ci * 49 + api[u] * 7 + apj[v];
            acc += zbuf[((t << 10) + qq) * PD + d];
        }
    }
    out[idx] = acc / (float)(ni * nj);
}

// ---------------------------------------------------------------------------
extern "C" void kernel_launch(void* const* d_in, const int* in_sizes, int n_in,
                              void* d_out, int out_size)
{
    const float* vid = (const float*)d_in[0];
    const float* gw  = (const float*)d_in[1];
    const float* gb  = (const float*)d_in[2];
    const float* thw = (const float*)d_in[3];
    const float* thb = (const float*)d_in[4];
    float* out = (float*)d_out;

    int conv_sm = (9216 + 1024 + 2592) * 4;
    int main_sm = SMF * 4;
    cudaFuncSetAttribute(conv_kernel, cudaFuncAttributeMaxDynamicSharedMemorySize, conv_sm);
    cudaFuncSetAttribute(main_kernel, cudaFuncAttributeMaxDynamicSharedMemorySize, main_sm);

    nudge_kernel<<<1, 32>>>();                                   // idx 0 (mod 6)
    conv_kernel<<<dim3(64, T), 256, conv_sm>>>(vid, gw, gb, thw, thb);  // idx 1
    nudge_kernel<<<1, 32>>>();                                   // idx 2
    main_kernel<<<dim3(NQ, T), 256, main_sm>>>();                // idx 3  <- ncu slot 15
    int ntot = T * NCI * H * W;
    final_kernel<<<(ntot + 255) / 256, 256>>>(out);              // idx 4
    nudge_kernel<<<1, 32>>>();                                   // idx 5
}